// round 11
// baseline (speedup 1.0000x reference)
#include <cuda_runtime.h>
#include <cuda_bf16.h>
#include <cstdint>

#define NN 100000
#define NE 1600000
#define FD 128
#define NG 128
#define FO 64
#define NBLK 98            // ceil(NN/1024)
#define GPART 1024         // gather grid / #stat partials
#define GEMM_GRID 782      // ceil(NN/128)
#define LDA 136            // bf16 elements per smem row (272B, conflict-free)
#define GEMM_SMEM (4 * 128 * LDA * 2)   // 139264 B

// ---------------- device scratch ----------------
__device__ __align__(16) unsigned int d_hsb[NN * FD / 2];  // h as bf16 pairs (per layer)
__device__ __align__(16) float d_z[NN * FD];               // pre-BN layer output
__device__ float d_dinv[NN];
__device__ int   d_degcnt[NN];
__device__ int   d_rowtmp[NN];
__device__ int   d_rs[NN + 1];
__device__ int   d_cur[NN];
__device__ int   d_csr[NE];
__device__ int   d_bsum[NBLK];
__device__ int   d_boff[128];
__device__ float d_part[GPART * 256];
__device__ float d_bnscale[2 * FD];
__device__ float d_bnshift[2 * FD];
__device__ __align__(16) float d_pooled[NG * FD];
__device__ int   d_gcnt[NG];
__device__ int   d_is64;
__device__ __align__(16) unsigned short d_whi[2][FD * FD];  // W^T split hi (bf16 bits), [n][k]
__device__ __align__(16) unsigned short d_wlo[2][FD * FD];  // W^T split lo

// ---------------- helpers ----------------
__device__ __forceinline__ uint32_t smem_to_u32(const void* p) {
    uint32_t a;
    asm("{ .reg .u64 t; cvta.to.shared.u64 t, %1; cvt.u32.u64 %0, t; }" : "=r"(a) : "l"(p));
    return a;
}
__device__ __forceinline__ void ldsm_x4(uint32_t addr, uint32_t* r) {
    asm volatile("ldmatrix.sync.aligned.m8n8.x4.shared.b16 {%0,%1,%2,%3}, [%4];"
                 : "=r"(r[0]), "=r"(r[1]), "=r"(r[2]), "=r"(r[3]) : "r"(addr));
}
__device__ __forceinline__ void ldsm_x2(uint32_t addr, uint32_t* r) {
    asm volatile("ldmatrix.sync.aligned.m8n8.x2.shared.b16 {%0,%1}, [%2];"
                 : "=r"(r[0]), "=r"(r[1]) : "r"(addr));
}
__device__ __forceinline__ void mma_bf16(float* c, const uint32_t* a, const uint32_t* b) {
    asm volatile("mma.sync.aligned.m16n8k16.row.col.f32.bf16.bf16.f32 "
                 "{%0,%1,%2,%3}, {%4,%5,%6,%7}, {%8,%9}, {%0,%1,%2,%3};"
                 : "+f"(c[0]), "+f"(c[1]), "+f"(c[2]), "+f"(c[3])
                 : "r"(a[0]), "r"(a[1]), "r"(a[2]), "r"(a[3]), "r"(b[0]), "r"(b[1]));
}
__device__ __forceinline__ int load_idx(const void* p, long long i) {
    if (d_is64) return (int)((const long long*)p)[i];
    return ((const int*)p)[i];
}
__device__ __forceinline__ void red_add_v4(float* dst, float4 v) {
    asm volatile("red.global.add.v4.f32 [%0], {%1, %2, %3, %4};"
                 :: "l"(dst), "f"(v.x), "f"(v.y), "f"(v.z), "f"(v.w) : "memory");
}
__device__ __forceinline__ uint32_t pack_bf2(float a, float b) {
    unsigned short la = __bfloat16_as_ushort(__float2bfloat16(a));
    unsigned short lb = __bfloat16_as_ushort(__float2bfloat16(b));
    return ((uint32_t)lb << 16) | la;
}
__device__ __forceinline__ float bf_res(float a) {   // a - bf16(a)
    return a - __bfloat162float(__float2bfloat16(a));
}
__device__ __forceinline__ float blo(uint32_t w) { return __uint_as_float(w << 16); }
__device__ __forceinline__ float bhi(uint32_t w) { return __uint_as_float(w & 0xffff0000u); }

// ---------------- kernels ----------------

// zero init + int64 detection fused
__global__ void init_kernel(const unsigned int* ei32) {
    int i = blockIdx.x * blockDim.x + threadIdx.x;
    if (i < NN) d_degcnt[i] = 0;
    if (i < NG * FD) d_pooled[i] = 0.0f;
    if (i < NG) d_gcnt[i] = 0;
    if (i == 0) {
        int is64 = 1;
        for (int k = 0; k < 128; k++)
            if (ei32[2 * k + 1] != 0u) { is64 = 0; break; }
        d_is64 = is64;
    }
}

// split W (fp32 [k][n]) into bf16 hi/lo transposed [n][k]
__global__ void wsplit_kernel(const float* __restrict__ W, int which) {
    int i = blockIdx.x * 256 + threadIdx.x;
    int k = i >> 7, n = i & 127;
    float w = W[i];
    __nv_bfloat16 h = __float2bfloat16(w);
    float hf = __bfloat162float(h);
    d_whi[which][n * FD + k] = __bfloat16_as_ushort(h);
    d_wlo[which][n * FD + k] = __bfloat16_as_ushort(__float2bfloat16(w - hf));
}

__global__ void deg_kernel(const void* ei) {
    int i = blockIdx.x * blockDim.x + threadIdx.x;
    if (i < NE) atomicAdd(&d_degcnt[load_idx(ei, (long long)NE + i)], 1);
}

__global__ void gcount_kernel(const void* batch) {
    int i = blockIdx.x * blockDim.x + threadIdx.x;
    if (i < NN) atomicAdd(&d_gcnt[load_idx(batch, i)], 1);
}

__global__ void scanA_kernel() {
    __shared__ int sm[1024];
    int i = blockIdx.x * 1024 + threadIdx.x;
    int v = (i < NN) ? d_degcnt[i] : 0;
    sm[threadIdx.x] = v;
    __syncthreads();
#pragma unroll
    for (int off = 1; off < 1024; off <<= 1) {
        int t = (threadIdx.x >= off) ? sm[threadIdx.x - off] : 0;
        __syncthreads();
        sm[threadIdx.x] += t;
        __syncthreads();
    }
    if (i < NN) d_rowtmp[i] = sm[threadIdx.x];
    if (threadIdx.x == 1023) d_bsum[blockIdx.x] = sm[1023];
}

__global__ void scanB_kernel() {
    __shared__ int sm[128];
    int t = threadIdx.x;
    sm[t] = (t < NBLK) ? d_bsum[t] : 0;
    __syncthreads();
#pragma unroll
    for (int off = 1; off < 128; off <<= 1) {
        int v = (t >= off) ? sm[t - off] : 0;
        __syncthreads();
        sm[t] += v;
        __syncthreads();
    }
    d_boff[t] = sm[t];
}

__global__ void scanC_kernel() {
    int i = blockIdx.x * 1024 + threadIdx.x;
    if (i >= NN) return;
    int blk = blockIdx.x;
    int off = (blk == 0) ? 0 : d_boff[blk - 1];
    int deg = d_degcnt[i];
    int incl = d_rowtmp[i] + off;
    d_rs[i + 1] = incl;
    d_cur[i] = incl - deg;
    d_dinv[i] = rsqrtf((float)(deg + 1));
    if (i == 0) d_rs[0] = 0;
}

__global__ void csr_fill_kernel(const void* ei) {
    int i = blockIdx.x * blockDim.x + threadIdx.x;
    if (i >= NE) return;
    int s = load_idx(ei, i);
    int d = load_idx(ei, (long long)NE + i);
    int pos = atomicAdd(&d_cur[d], 1);
    d_csr[pos] = s;
}

// bf16-split tensor-core GEMM via mma.sync: d_hsb[tile] = bf16( bnrelu?(A) @ W )
__global__ __launch_bounds__(256) void gemm_mma_kernel(const float* __restrict__ Aext, int layer) {
    extern __shared__ __align__(16) char sm_raw[];
    unsigned short* sAhi = (unsigned short*)sm_raw;          // [128][LDA]
    unsigned short* sAlo = sAhi + 128 * LDA;
    unsigned short* sBhi = sAlo + 128 * LDA;                 // W^T [n][k]
    unsigned short* sBlo = sBhi + 128 * LDA;

    const float* A = (layer == 0) ? Aext : d_z;
    int tid = threadIdx.x;
    int lane = tid & 31, wid = tid >> 5;
    int bm = blockIdx.x * 128;

    // ---- stage A (fp32 load, optional BN+ReLU, bf16 hi/lo split) and B (copy) ----
    {
        int row = tid & 127;
        int half = tid >> 7;
        int grow = bm + row;
        const float* ap = A + (long long)grow * FD;
#pragma unroll
        for (int g = 0; g < 8; g++) {
            int c = half * 64 + g * 8;
            float4 v0 = make_float4(0.f, 0.f, 0.f, 0.f);
            float4 v1 = v0;
            if (grow < NN) {
                v0 = *(const float4*)(ap + c);
                v1 = *(const float4*)(ap + c + 4);
            }
            if (layer == 1) {
                float4 sc0 = *(const float4*)&d_bnscale[c];
                float4 sh0 = *(const float4*)&d_bnshift[c];
                float4 sc1 = *(const float4*)&d_bnscale[c + 4];
                float4 sh1 = *(const float4*)&d_bnshift[c + 4];
                v0.x = fmaxf(fmaf(v0.x, sc0.x, sh0.x), 0.f);
                v0.y = fmaxf(fmaf(v0.y, sc0.y, sh0.y), 0.f);
                v0.z = fmaxf(fmaf(v0.z, sc0.z, sh0.z), 0.f);
                v0.w = fmaxf(fmaf(v0.w, sc0.w, sh0.w), 0.f);
                v1.x = fmaxf(fmaf(v1.x, sc1.x, sh1.x), 0.f);
                v1.y = fmaxf(fmaf(v1.y, sc1.y, sh1.y), 0.f);
                v1.z = fmaxf(fmaf(v1.z, sc1.z, sh1.z), 0.f);
                v1.w = fmaxf(fmaf(v1.w, sc1.w, sh1.w), 0.f);
            }
            uint4 hi, lo;
            hi.x = pack_bf2(v0.x, v0.y); hi.y = pack_bf2(v0.z, v0.w);
            hi.z = pack_bf2(v1.x, v1.y); hi.w = pack_bf2(v1.z, v1.w);
            lo.x = pack_bf2(bf_res(v0.x), bf_res(v0.y));
            lo.y = pack_bf2(bf_res(v0.z), bf_res(v0.w));
            lo.z = pack_bf2(bf_res(v1.x), bf_res(v1.y));
            lo.w = pack_bf2(bf_res(v1.z), bf_res(v1.w));
            *(uint4*)(sAhi + row * LDA + c) = hi;
            *(uint4*)(sAlo + row * LDA + c) = lo;
        }
        const unsigned short* wh = &d_whi[layer][row * FD + half * 64];
        const unsigned short* wl = &d_wlo[layer][row * FD + half * 64];
#pragma unroll
        for (int g = 0; g < 8; g++) {
            *(uint4*)(sBhi + row * LDA + half * 64 + g * 8) = *(const uint4*)(wh + g * 8);
            *(uint4*)(sBlo + row * LDA + half * 64 + g * 8) = *(const uint4*)(wl + g * 8);
        }
    }
    __syncthreads();

    // ---- compute ----
    int wm = wid & 3, wn = wid >> 2;
    int m0 = wm * 32, n0 = wn * 64;

    float acc[2][8][4];
#pragma unroll
    for (int im = 0; im < 2; im++)
#pragma unroll
        for (int in = 0; in < 8; in++)
#pragma unroll
            for (int c = 0; c < 4; c++) acc[im][in][c] = 0.f;

    int r8 = lane & 7;
    int g1 = (lane >> 3) & 1;
    int g2 = lane >> 4;
    uint32_t aHi = smem_to_u32(sAhi) + (uint32_t)(((m0 + g1 * 8 + r8) * LDA + g2 * 8) * 2);
    uint32_t aLo = aHi + 128 * LDA * 2;
    uint32_t bHi = smem_to_u32(sBhi) + (uint32_t)(((n0 + r8) * LDA + g1 * 8) * 2);
    uint32_t bLo = bHi + 128 * LDA * 2;

#pragma unroll
    for (int ks = 0; ks < 8; ks++) {
        uint32_t ko = ks * 32;
        uint32_t ahi[2][4], alo[2][4];
        ldsm_x4(aHi + ko, ahi[0]);
        ldsm_x4(aHi + 16 * LDA * 2 + ko, ahi[1]);
        ldsm_x4(aLo + ko, alo[0]);
        ldsm_x4(aLo + 16 * LDA * 2 + ko, alo[1]);
        uint32_t bhiV[8][2], bloV[8][2];
#pragma unroll
        for (int in = 0; in < 8; in++) {
            ldsm_x2(bHi + in * (8 * LDA * 2) + ko, bhiV[in]);
            ldsm_x2(bLo + in * (8 * LDA * 2) + ko, bloV[in]);
        }
#pragma unroll
        for (int im = 0; im < 2; im++)
#pragma unroll
            for (int in = 0; in < 8; in++) {
                mma_bf16(acc[im][in], ahi[im], bhiV[in]);
                mma_bf16(acc[im][in], ahi[im], bloV[in]);
                mma_bf16(acc[im][in], alo[im], bhiV[in]);
            }
    }

    // ---- epilogue: acc -> d_hsb (bf16 pairs) ----
    int rlo = lane >> 2;
    int cbase = (lane & 3) * 2;
#pragma unroll
    for (int im = 0; im < 2; im++) {
        int row0 = bm + m0 + im * 16 + rlo;
        int row1 = row0 + 8;
#pragma unroll
        for (int in = 0; in < 8; in++) {
            int col = n0 + in * 8 + cbase;
            if (row0 < NN)
                d_hsb[(long long)row0 * 64 + (col >> 1)] = pack_bf2(acc[im][in][0], acc[im][in][1]);
            if (row1 < NN)
                d_hsb[(long long)row1 * 64 + (col >> 1)] = pack_bf2(acc[im][in][2], acc[im][in][3]);
        }
    }
}

// warp per node (strided): z[n] = dinv[n]*( sum_nbr dinv[s]*h[s] + dinv[n]*h[n] ) + bias
// h read as bf16 pairs (uint2 = 4 features / lane).
__global__ __launch_bounds__(256) void gather_kernel(const float* __restrict__ bias) {
    __shared__ float red[8][256];
    int lane = threadIdx.x & 31;
    int warp = threadIdx.x >> 5;
    int gw = blockIdx.x * 8 + warp;
    float b0 = bias[lane * 4 + 0];
    float b1 = bias[lane * 4 + 1];
    float b2 = bias[lane * 4 + 2];
    float b3 = bias[lane * 4 + 3];

    float4 s = make_float4(0.f, 0.f, 0.f, 0.f);
    float4 q = make_float4(0.f, 0.f, 0.f, 0.f);

    for (int n = gw; n < NN; n += GPART * 8) {
        int rs = d_rs[n];
        int re = d_rs[n + 1];
        float dv = d_dinv[n];
        uint2 sv = __ldg((const uint2*)(d_hsb + (long long)n * 64) + lane);
        float4 acc = make_float4(blo(sv.x) * dv, bhi(sv.x) * dv, blo(sv.y) * dv, bhi(sv.y) * dv);

        int j = rs;
        for (; j + 4 <= re; j += 4) {
            int i0 = d_csr[j], i1 = d_csr[j + 1], i2 = d_csr[j + 2], i3 = d_csr[j + 3];
            float e0 = d_dinv[i0], e1 = d_dinv[i1], e2 = d_dinv[i2], e3 = d_dinv[i3];
            uint2 v0 = __ldg((const uint2*)(d_hsb + (long long)i0 * 64) + lane);
            uint2 v1 = __ldg((const uint2*)(d_hsb + (long long)i1 * 64) + lane);
            uint2 v2 = __ldg((const uint2*)(d_hsb + (long long)i2 * 64) + lane);
            uint2 v3 = __ldg((const uint2*)(d_hsb + (long long)i3 * 64) + lane);
            acc.x = fmaf(blo(v0.x), e0, acc.x); acc.y = fmaf(bhi(v0.x), e0, acc.y);
            acc.z = fmaf(blo(v0.y), e0, acc.z); acc.w = fmaf(bhi(v0.y), e0, acc.w);
            acc.x = fmaf(blo(v1.x), e1, acc.x); acc.y = fmaf(bhi(v1.x), e1, acc.y);
            acc.z = fmaf(blo(v1.y), e1, acc.z); acc.w = fmaf(bhi(v1.y), e1, acc.w);
            acc.x = fmaf(blo(v2.x), e2, acc.x); acc.y = fmaf(bhi(v2.x), e2, acc.y);
            acc.z = fmaf(blo(v2.y), e2, acc.z); acc.w = fmaf(bhi(v2.y), e2, acc.w);
            acc.x = fmaf(blo(v3.x), e3, acc.x); acc.y = fmaf(bhi(v3.x), e3, acc.y);
            acc.z = fmaf(blo(v3.y), e3, acc.z); acc.w = fmaf(bhi(v3.y), e3, acc.w);
        }
        for (; j < re; j++) {
            int i0 = d_csr[j];
            float e0 = d_dinv[i0];
            uint2 v0 = __ldg((const uint2*)(d_hsb + (long long)i0 * 64) + lane);
            acc.x = fmaf(blo(v0.x), e0, acc.x); acc.y = fmaf(bhi(v0.x), e0, acc.y);
            acc.z = fmaf(blo(v0.y), e0, acc.z); acc.w = fmaf(bhi(v0.y), e0, acc.w);
        }

        float4 z;
        z.x = fmaf(acc.x, dv, b0);
        z.y = fmaf(acc.y, dv, b1);
        z.z = fmaf(acc.z, dv, b2);
        z.w = fmaf(acc.w, dv, b3);
        *((float4*)(d_z + (long long)n * FD) + lane) = z;

        s.x += z.x; s.y += z.y; s.z += z.z; s.w += z.w;
        q.x = fmaf(z.x, z.x, q.x); q.y = fmaf(z.y, z.y, q.y);
        q.z = fmaf(z.z, z.z, q.z); q.w = fmaf(z.w, z.w, q.w);
    }

    red[warp][lane * 4 + 0] = s.x; red[warp][lane * 4 + 1] = s.y;
    red[warp][lane * 4 + 2] = s.z; red[warp][lane * 4 + 3] = s.w;
    red[warp][128 + lane * 4 + 0] = q.x; red[warp][128 + lane * 4 + 1] = q.y;
    red[warp][128 + lane * 4 + 2] = q.z; red[warp][128 + lane * 4 + 3] = q.w;
    __syncthreads();
    int c = threadIdx.x;
    float t = 0.f;
#pragma unroll
    for (int w = 0; w < 8; w++) t += red[w][c];
    d_part[blockIdx.x * 256 + c] = t;
}

__global__ void bnstats_kernel(const float* __restrict__ g, const float* __restrict__ be, int layer) {
    __shared__ float ss[128], qq[128];
    int f = blockIdx.x;
    int t = threadIdx.x;
    if (t < 128) {
        float v = 0.f;
#pragma unroll
        for (int k = 0; k < GPART / 128; k++) v += d_part[(t + 128 * k) * 256 + f];
        ss[t] = v;
    } else {
        int tt = t - 128;
        float v = 0.f;
#pragma unroll
        for (int k = 0; k < GPART / 128; k++) v += d_part[(tt + 128 * k) * 256 + 128 + f];
        qq[tt] = v;
    }
    __syncthreads();
#pragma unroll
    for (int off = 64; off > 0; off >>= 1) {
        if (t < off) ss[t] += ss[t + off];
        else if (t >= 128 && t < 128 + off) qq[t - 128] += qq[t - 128 + off];
        __syncthreads();
    }
    if (t == 0) {
        float inv_n = 1.0f / (float)NN;
        float mu = ss[0] * inv_n;
        float ms = qq[0] * inv_n;
        float var = ms - mu * mu;
        float sc = g[f] * rsqrtf(var + 1e-5f);
        d_bnscale[layer * FD + f] = sc;
        d_bnshift[layer * FD + f] = be[f] - mu * sc;
    }
}

__global__ __launch_bounds__(256) void pool_kernel(const void* batch) {
    long long gt = (long long)blockIdx.x * blockDim.x + threadIdx.x;
    long long n = gt >> 5;
    int lane = threadIdx.x & 31;
    if (n >= NN) return;
    int g = load_idx(batch, n);
    int f = lane * 4;
    float4 v = *(const float4*)(d_z + n * FD + f);
    float4 sc = *(const float4*)&d_bnscale[FD + f];
    float4 sh = *(const float4*)&d_bnshift[FD + f];
    v.x = fmaxf(fmaf(v.x, sc.x, sh.x), 0.f);
    v.y = fmaxf(fmaf(v.y, sc.y, sh.y), 0.f);
    v.z = fmaxf(fmaf(v.z, sc.z, sh.z), 0.f);
    v.w = fmaxf(fmaf(v.w, sc.w, sh.w), 0.f);
    red_add_v4(d_pooled + (long long)g * FD + f, v);
}

__global__ void out_kernel(const float* __restrict__ Wout, const float* __restrict__ bout,
                           float* __restrict__ out) {
    int g = blockIdx.x;
    int o = threadIdx.x;
    float inv = 1.0f / fmaxf((float)d_gcnt[g], 1.0f);
    float acc = 0.f;
#pragma unroll 8
    for (int h = 0; h < FD; h++) acc += d_pooled[g * FD + h] * Wout[h * FO + o];
    out[g * FO + o] = acc * inv + bout[o];
}

// ---------------- launch ----------------
extern "C" void kernel_launch(void* const* d_in, const int* in_sizes, int n_in,
                              void* d_out, int out_size) {
    int ii = 0;
    auto nxt = [&]() -> const void* {
        while (ii < n_in && in_sizes[ii] == 1) ii++;
        return d_in[ii++];
    };
    const float* x   = (const float*)nxt();
    const void*  ei  = nxt();
    const void*  bat = nxt();
    const float* W0  = (const float*)nxt();
    const float* b0  = (const float*)nxt();
    const float* g0  = (const float*)nxt();
    const float* be0 = (const float*)nxt();
    const float* W1  = (const float*)nxt();
    const float* b1  = (const float*)nxt();
    const float* g1  = (const float*)nxt();
    const float* be1 = (const float*)nxt();
    const float* Wo  = (const float*)nxt();
    const float* bo  = (const float*)nxt();
    float* out = (float*)d_out;

    static int inited = 0;
    static cudaStream_t s1 = 0, s2 = 0;
    static cudaEvent_t e0 = 0, e1 = 0, e2 = 0;
    if (!inited) {
        cudaFuncSetAttribute(gemm_mma_kernel, cudaFuncAttributeMaxDynamicSharedMemorySize, GEMM_SMEM);
        if (cudaStreamCreateWithFlags(&s1, cudaStreamNonBlocking) != cudaSuccess) s1 = 0;
        if (cudaStreamCreateWithFlags(&s2, cudaStreamNonBlocking) != cudaSuccess) s2 = 0;
        cudaEventCreateWithFlags(&e0, cudaEventDisableTiming);
        cudaEventCreateWithFlags(&e1, cudaEventDisableTiming);
        cudaEventCreateWithFlags(&e2, cudaEventDisableTiming);
        inited = 1;
    }

    // main stream: init + CSR chain
    init_kernel<<<(NN + 255) / 256, 256>>>((const unsigned int*)ei);
    cudaEventRecord(e0, 0);

    // stream 1: weight split + layer-0 GEMM (independent of CSR)
    cudaStreamWaitEvent(s1, e0, 0);
    wsplit_kernel<<<64, 256, 0, s1>>>(W0, 0);
    wsplit_kernel<<<64, 256, 0, s1>>>(W1, 1);
    gemm_mma_kernel<<<GEMM_GRID, 256, GEMM_SMEM, s1>>>(x, 0);
    cudaEventRecord(e1, s1);

    // stream 2: graph-id histogram (only needed by out_kernel)
    cudaStreamWaitEvent(s2, e0, 0);
    gcount_kernel<<<(NN + 255) / 256, 256, 0, s2>>>(bat);
    cudaEventRecord(e2, s2);

    // main stream: CSR build
    deg_kernel<<<(NE + 255) / 256, 256>>>(ei);
    scanA_kernel<<<NBLK, 1024>>>();
    scanB_kernel<<<1, 128>>>();
    scanC_kernel<<<NBLK, 1024>>>();
    csr_fill_kernel<<<(NE + 255) / 256, 256>>>(ei);

    // join GEMM0, then layer pipeline
    cudaStreamWaitEvent(0, e1, 0);
    gather_kernel<<<GPART, 256>>>(b0);
    bnstats_kernel<<<FD, 256>>>(g0, be0, 0);

    gemm_mma_kernel<<<GEMM_GRID, 256, GEMM_SMEM>>>(nullptr, 1);
    gather_kernel<<<GPART, 256>>>(b1);
    bnstats_kernel<<<FD, 256>>>(g1, be1, 1);

    pool_kernel<<<(int)(((long long)NN * 32 + 255) / 256), 256>>>(bat);
    cudaStreamWaitEvent(0, e2, 0);
    out_kernel<<<NG, FO>>>(Wo, bo, out);
}

// round 12
// speedup vs baseline: 1.3450x; 1.3450x over previous
#include <cuda_runtime.h>
#include <cuda_bf16.h>
#include <cstdint>

#define NN 100000
#define NE 1600000
#define FD 128
#define NG 128
#define FO 64
#define NBLK 98            // ceil(NN/1024)
#define GPART 1024         // gather grid / #stat partials
#define GEMM_GRID 782      // ceil(NN/128)
#define LDK 72             // bf16 elements per smem row (144B, ldmatrix conflict-free)
#define GEMM_SMEM (4 * 128 * LDK * 2)   // 73728 B -> 3 CTAs/SM

// ---------------- device scratch ----------------
__device__ __align__(16) unsigned int d_hsb[NN * FD / 2];  // h as bf16 pairs (per layer)
__device__ __align__(16) float d_z[NN * FD];               // pre-BN layer output
__device__ float d_dinv[NN];
__device__ int   d_degcnt[NN];
__device__ int   d_rowtmp[NN];
__device__ int   d_rs[NN + 1];
__device__ int   d_cur[NN];
__device__ int   d_csr[NE];
__device__ int   d_bsum[NBLK];
__device__ int   d_boff[128];
__device__ float d_part[GPART * 256];
__device__ float d_bnscale[2 * FD];
__device__ float d_bnshift[2 * FD];
__device__ __align__(16) float d_pooled[NG * FD];
__device__ int   d_gcnt[NG];
__device__ int   d_is64;
__device__ __align__(16) unsigned short d_whi[2][FD * FD];  // W^T split hi (bf16 bits), [n][k]
__device__ __align__(16) unsigned short d_wlo[2][FD * FD];  // W^T split lo

// ---------------- helpers ----------------
__device__ __forceinline__ uint32_t smem_to_u32(const void* p) {
    uint32_t a;
    asm("{ .reg .u64 t; cvta.to.shared.u64 t, %1; cvt.u32.u64 %0, t; }" : "=r"(a) : "l"(p));
    return a;
}
__device__ __forceinline__ void ldsm_x4(uint32_t addr, uint32_t* r) {
    asm volatile("ldmatrix.sync.aligned.m8n8.x4.shared.b16 {%0,%1,%2,%3}, [%4];"
                 : "=r"(r[0]), "=r"(r[1]), "=r"(r[2]), "=r"(r[3]) : "r"(addr));
}
__device__ __forceinline__ void ldsm_x2(uint32_t addr, uint32_t* r) {
    asm volatile("ldmatrix.sync.aligned.m8n8.x2.shared.b16 {%0,%1}, [%2];"
                 : "=r"(r[0]), "=r"(r[1]) : "r"(addr));
}
__device__ __forceinline__ void mma_bf16(float* c, const uint32_t* a, const uint32_t* b) {
    asm volatile("mma.sync.aligned.m16n8k16.row.col.f32.bf16.bf16.f32 "
                 "{%0,%1,%2,%3}, {%4,%5,%6,%7}, {%8,%9}, {%0,%1,%2,%3};"
                 : "+f"(c[0]), "+f"(c[1]), "+f"(c[2]), "+f"(c[3])
                 : "r"(a[0]), "r"(a[1]), "r"(a[2]), "r"(a[3]), "r"(b[0]), "r"(b[1]));
}
__device__ __forceinline__ int load_idx(const void* p, long long i) {
    if (d_is64) return (int)((const long long*)p)[i];
    return ((const int*)p)[i];
}
__device__ __forceinline__ void red_add_v4(float* dst, float4 v) {
    asm volatile("red.global.add.v4.f32 [%0], {%1, %2, %3, %4};"
                 :: "l"(dst), "f"(v.x), "f"(v.y), "f"(v.z), "f"(v.w) : "memory");
}
__device__ __forceinline__ uint32_t pack_bf2(float a, float b) {
    unsigned short la = __bfloat16_as_ushort(__float2bfloat16(a));
    unsigned short lb = __bfloat16_as_ushort(__float2bfloat16(b));
    return ((uint32_t)lb << 16) | la;
}
__device__ __forceinline__ float bf_res(float a) {   // a - bf16(a)
    return a - __bfloat162float(__float2bfloat16(a));
}
__device__ __forceinline__ float blo(uint32_t w) { return __uint_as_float(w << 16); }
__device__ __forceinline__ float bhi(uint32_t w) { return __uint_as_float(w & 0xffff0000u); }

// ---------------- kernels ----------------

// zero init + int64 detection fused
__global__ void init_kernel(const unsigned int* ei32) {
    int i = blockIdx.x * blockDim.x + threadIdx.x;
    if (i < NN) d_degcnt[i] = 0;
    if (i < NG * FD) d_pooled[i] = 0.0f;
    if (i < NG) d_gcnt[i] = 0;
    if (i == 0) {
        int is64 = 1;
        for (int k = 0; k < 128; k++)
            if (ei32[2 * k + 1] != 0u) { is64 = 0; break; }
        d_is64 = is64;
    }
}

// split W (fp32 [k][n]) into bf16 hi/lo transposed [n][k]
__global__ void wsplit_kernel(const float* __restrict__ W, int which) {
    int i = blockIdx.x * 256 + threadIdx.x;
    int k = i >> 7, n = i & 127;
    float w = W[i];
    __nv_bfloat16 h = __float2bfloat16(w);
    float hf = __bfloat162float(h);
    d_whi[which][n * FD + k] = __bfloat16_as_ushort(h);
    d_wlo[which][n * FD + k] = __bfloat16_as_ushort(__float2bfloat16(w - hf));
}

__global__ void deg_kernel(const void* ei) {
    int i = blockIdx.x * blockDim.x + threadIdx.x;
    if (i < NE) atomicAdd(&d_degcnt[load_idx(ei, (long long)NE + i)], 1);
}

__global__ void gcount_kernel(const void* batch) {
    int i = blockIdx.x * blockDim.x + threadIdx.x;
    if (i < NN) atomicAdd(&d_gcnt[load_idx(batch, i)], 1);
}

__global__ void scanA_kernel() {
    __shared__ int sm[1024];
    int i = blockIdx.x * 1024 + threadIdx.x;
    int v = (i < NN) ? d_degcnt[i] : 0;
    sm[threadIdx.x] = v;
    __syncthreads();
#pragma unroll
    for (int off = 1; off < 1024; off <<= 1) {
        int t = (threadIdx.x >= off) ? sm[threadIdx.x - off] : 0;
        __syncthreads();
        sm[threadIdx.x] += t;
        __syncthreads();
    }
    if (i < NN) d_rowtmp[i] = sm[threadIdx.x];
    if (threadIdx.x == 1023) d_bsum[blockIdx.x] = sm[1023];
}

__global__ void scanB_kernel() {
    __shared__ int sm[128];
    int t = threadIdx.x;
    sm[t] = (t < NBLK) ? d_bsum[t] : 0;
    __syncthreads();
#pragma unroll
    for (int off = 1; off < 128; off <<= 1) {
        int v = (t >= off) ? sm[t - off] : 0;
        __syncthreads();
        sm[t] += v;
        __syncthreads();
    }
    d_boff[t] = sm[t];
}

__global__ void scanC_kernel() {
    int i = blockIdx.x * 1024 + threadIdx.x;
    if (i >= NN) return;
    int blk = blockIdx.x;
    int off = (blk == 0) ? 0 : d_boff[blk - 1];
    int deg = d_degcnt[i];
    int incl = d_rowtmp[i] + off;
    d_rs[i + 1] = incl;
    d_cur[i] = incl - deg;
    d_dinv[i] = rsqrtf((float)(deg + 1));
    if (i == 0) d_rs[0] = 0;
}

__global__ void csr_fill_kernel(const void* ei) {
    int i = blockIdx.x * blockDim.x + threadIdx.x;
    if (i >= NE) return;
    int s = load_idx(ei, i);
    int d = load_idx(ei, (long long)NE + i);
    int pos = atomicAdd(&d_cur[d], 1);
    d_csr[pos] = s;
}

// bf16-split tensor-core GEMM via mma.sync, K split in 2 halves (smem reuse -> 3 CTAs/SM).
// d_hsb[tile] = bf16( bnrelu?(A) @ W );  M=128, N=128, K=128.
__global__ __launch_bounds__(256) void gemm_mma_kernel(const float* __restrict__ Aext, int layer) {
    extern __shared__ __align__(16) char sm_raw[];
    unsigned short* sAhi = (unsigned short*)sm_raw;          // [128][LDK]
    unsigned short* sAlo = sAhi + 128 * LDK;
    unsigned short* sBhi = sAlo + 128 * LDK;                 // W^T [n][k-half]
    unsigned short* sBlo = sBhi + 128 * LDK;

    const float* A = (layer == 0) ? Aext : d_z;
    int tid = threadIdx.x;
    int lane = tid & 31, wid = tid >> 5;
    int bm = blockIdx.x * 128;

    int wm = wid & 3, wn = wid >> 2;
    int m0 = wm * 32, n0 = wn * 64;

    float acc[2][8][4];
#pragma unroll
    for (int im = 0; im < 2; im++)
#pragma unroll
        for (int in = 0; in < 8; in++)
#pragma unroll
            for (int c = 0; c < 4; c++) acc[im][in][c] = 0.f;

    int r8 = lane & 7;
    int g1 = (lane >> 3) & 1;
    int g2 = lane >> 4;
    uint32_t aHi = smem_to_u32(sAhi) + (uint32_t)(((m0 + g1 * 8 + r8) * LDK + g2 * 8) * 2);
    uint32_t aLo = aHi + 128 * LDK * 2;
    uint32_t bHi = smem_to_u32(sBhi) + (uint32_t)(((n0 + r8) * LDK + g1 * 8) * 2);
    uint32_t bLo = bHi + 128 * LDK * 2;

    int srow = tid & 127;               // staging row
    int shalf = tid >> 7;               // 0: cols 0-31, 1: cols 32-63 of the half
    int grow = bm + srow;
    const float* aprow = A + (long long)grow * FD;

#pragma unroll
    for (int kh = 0; kh < 2; kh++) {
        int k0 = kh * 64;
        // ---- stage A (fp32 load, optional BN+ReLU, bf16 hi/lo split) ----
#pragma unroll
        for (int g = 0; g < 4; g++) {
            int c = shalf * 32 + g * 8;          // col within half
            int f = k0 + c;                      // global feature col
            float4 v0 = make_float4(0.f, 0.f, 0.f, 0.f);
            float4 v1 = v0;
            if (grow < NN) {
                v0 = *(const float4*)(aprow + f);
                v1 = *(const float4*)(aprow + f + 4);
            }
            if (layer == 1) {
                float4 sc0 = *(const float4*)&d_bnscale[f];
                float4 sh0 = *(const float4*)&d_bnshift[f];
                float4 sc1 = *(const float4*)&d_bnscale[f + 4];
                float4 sh1 = *(const float4*)&d_bnshift[f + 4];
                v0.x = fmaxf(fmaf(v0.x, sc0.x, sh0.x), 0.f);
                v0.y = fmaxf(fmaf(v0.y, sc0.y, sh0.y), 0.f);
                v0.z = fmaxf(fmaf(v0.z, sc0.z, sh0.z), 0.f);
                v0.w = fmaxf(fmaf(v0.w, sc0.w, sh0.w), 0.f);
                v1.x = fmaxf(fmaf(v1.x, sc1.x, sh1.x), 0.f);
                v1.y = fmaxf(fmaf(v1.y, sc1.y, sh1.y), 0.f);
                v1.z = fmaxf(fmaf(v1.z, sc1.z, sh1.z), 0.f);
                v1.w = fmaxf(fmaf(v1.w, sc1.w, sh1.w), 0.f);
            }
            uint4 hi, lo;
            hi.x = pack_bf2(v0.x, v0.y); hi.y = pack_bf2(v0.z, v0.w);
            hi.z = pack_bf2(v1.x, v1.y); hi.w = pack_bf2(v1.z, v1.w);
            lo.x = pack_bf2(bf_res(v0.x), bf_res(v0.y));
            lo.y = pack_bf2(bf_res(v0.z), bf_res(v0.w));
            lo.z = pack_bf2(bf_res(v1.x), bf_res(v1.y));
            lo.w = pack_bf2(bf_res(v1.z), bf_res(v1.w));
            *(uint4*)(sAhi + srow * LDK + c) = hi;
            *(uint4*)(sAlo + srow * LDK + c) = lo;
        }
        // ---- stage B (copy pre-split W^T) ----
        {
            const unsigned short* wh = &d_whi[layer][srow * FD + k0 + shalf * 32];
            const unsigned short* wl = &d_wlo[layer][srow * FD + k0 + shalf * 32];
#pragma unroll
            for (int g = 0; g < 4; g++) {
                *(uint4*)(sBhi + srow * LDK + shalf * 32 + g * 8) = *(const uint4*)(wh + g * 8);
                *(uint4*)(sBlo + srow * LDK + shalf * 32 + g * 8) = *(const uint4*)(wl + g * 8);
            }
        }
        __syncthreads();

        // ---- compute 4 k-steps of this half ----
#pragma unroll
        for (int ks = 0; ks < 4; ks++) {
            uint32_t ko = ks * 32;
            uint32_t ahi[2][4], alo[2][4];
            ldsm_x4(aHi + ko, ahi[0]);
            ldsm_x4(aHi + 16 * LDK * 2 + ko, ahi[1]);
            ldsm_x4(aLo + ko, alo[0]);
            ldsm_x4(aLo + 16 * LDK * 2 + ko, alo[1]);
            uint32_t bhiV[8][2], bloV[8][2];
#pragma unroll
            for (int in = 0; in < 8; in++) {
                ldsm_x2(bHi + in * (8 * LDK * 2) + ko, bhiV[in]);
                ldsm_x2(bLo + in * (8 * LDK * 2) + ko, bloV[in]);
            }
#pragma unroll
            for (int im = 0; im < 2; im++)
#pragma unroll
                for (int in = 0; in < 8; in++) {
                    mma_bf16(acc[im][in], ahi[im], bhiV[in]);
                    mma_bf16(acc[im][in], ahi[im], bloV[in]);
                    mma_bf16(acc[im][in], alo[im], bhiV[in]);
                }
        }
        __syncthreads();
    }

    // ---- epilogue: acc -> d_hsb (bf16 pairs) ----
    int rlo = lane >> 2;
    int cbase = (lane & 3) * 2;
#pragma unroll
    for (int im = 0; im < 2; im++) {
        int row0 = bm + m0 + im * 16 + rlo;
        int row1 = row0 + 8;
#pragma unroll
        for (int in = 0; in < 8; in++) {
            int col = n0 + in * 8 + cbase;
            if (row0 < NN)
                d_hsb[(long long)row0 * 64 + (col >> 1)] = pack_bf2(acc[im][in][0], acc[im][in][1]);
            if (row1 < NN)
                d_hsb[(long long)row1 * 64 + (col >> 1)] = pack_bf2(acc[im][in][2], acc[im][in][3]);
        }
    }
}

// warp per node (strided): z[n] = dinv[n]*( sum_nbr dinv[s]*h[s] + dinv[n]*h[n] ) + bias
__global__ __launch_bounds__(256) void gather_kernel(const float* __restrict__ bias) {
    __shared__ float red[8][256];
    int lane = threadIdx.x & 31;
    int warp = threadIdx.x >> 5;
    int gw = blockIdx.x * 8 + warp;
    float b0 = bias[lane * 4 + 0];
    float b1 = bias[lane * 4 + 1];
    float b2 = bias[lane * 4 + 2];
    float b3 = bias[lane * 4 + 3];

    float4 s = make_float4(0.f, 0.f, 0.f, 0.f);
    float4 q = make_float4(0.f, 0.f, 0.f, 0.f);

    for (int n = gw; n < NN; n += GPART * 8) {
        int rs = d_rs[n];
        int re = d_rs[n + 1];
        float dv = d_dinv[n];
        uint2 sv = __ldg((const uint2*)(d_hsb + (long long)n * 64) + lane);
        float4 acc = make_float4(blo(sv.x) * dv, bhi(sv.x) * dv, blo(sv.y) * dv, bhi(sv.y) * dv);

        int j = rs;
        for (; j + 4 <= re; j += 4) {
            int i0 = d_csr[j], i1 = d_csr[j + 1], i2 = d_csr[j + 2], i3 = d_csr[j + 3];
            float e0 = d_dinv[i0], e1 = d_dinv[i1], e2 = d_dinv[i2], e3 = d_dinv[i3];
            uint2 v0 = __ldg((const uint2*)(d_hsb + (long long)i0 * 64) + lane);
            uint2 v1 = __ldg((const uint2*)(d_hsb + (long long)i1 * 64) + lane);
            uint2 v2 = __ldg((const uint2*)(d_hsb + (long long)i2 * 64) + lane);
            uint2 v3 = __ldg((const uint2*)(d_hsb + (long long)i3 * 64) + lane);
            acc.x = fmaf(blo(v0.x), e0, acc.x); acc.y = fmaf(bhi(v0.x), e0, acc.y);
            acc.z = fmaf(blo(v0.y), e0, acc.z); acc.w = fmaf(bhi(v0.y), e0, acc.w);
            acc.x = fmaf(blo(v1.x), e1, acc.x); acc.y = fmaf(bhi(v1.x), e1, acc.y);
            acc.z = fmaf(blo(v1.y), e1, acc.z); acc.w = fmaf(bhi(v1.y), e1, acc.w);
            acc.x = fmaf(blo(v2.x), e2, acc.x); acc.y = fmaf(bhi(v2.x), e2, acc.y);
            acc.z = fmaf(blo(v2.y), e2, acc.z); acc.w = fmaf(bhi(v2.y), e2, acc.w);
            acc.x = fmaf(blo(v3.x), e3, acc.x); acc.y = fmaf(bhi(v3.x), e3, acc.y);
            acc.z = fmaf(blo(v3.y), e3, acc.z); acc.w = fmaf(bhi(v3.y), e3, acc.w);
        }
        for (; j < re; j++) {
            int i0 = d_csr[j];
            float e0 = d_dinv[i0];
            uint2 v0 = __ldg((const uint2*)(d_hsb + (long long)i0 * 64) + lane);
            acc.x = fmaf(blo(v0.x), e0, acc.x); acc.y = fmaf(bhi(v0.x), e0, acc.y);
            acc.z = fmaf(blo(v0.y), e0, acc.z); acc.w = fmaf(bhi(v0.y), e0, acc.w);
        }

        float4 z;
        z.x = fmaf(acc.x, dv, b0);
        z.y = fmaf(acc.y, dv, b1);
        z.z = fmaf(acc.z, dv, b2);
        z.w = fmaf(acc.w, dv, b3);
        *((float4*)(d_z + (long long)n * FD) + lane) = z;

        s.x += z.x; s.y += z.y; s.z += z.z; s.w += z.w;
        q.x = fmaf(z.x, z.x, q.x); q.y = fmaf(z.y, z.y, q.y);
        q.z = fmaf(z.z, z.z, q.z); q.w = fmaf(z.w, z.w, q.w);
    }

    red[warp][lane * 4 + 0] = s.x; red[warp][lane * 4 + 1] = s.y;
    red[warp][lane * 4 + 2] = s.z; red[warp][lane * 4 + 3] = s.w;
    red[warp][128 + lane * 4 + 0] = q.x; red[warp][128 + lane * 4 + 1] = q.y;
    red[warp][128 + lane * 4 + 2] = q.z; red[warp][128 + lane * 4 + 3] = q.w;
    __syncthreads();
    int c = threadIdx.x;
    float t = 0.f;
#pragma unroll
    for (int w = 0; w < 8; w++) t += red[w][c];
    d_part[blockIdx.x * 256 + c] = t;
}

__global__ void bnstats_kernel(const float* __restrict__ g, const float* __restrict__ be, int layer) {
    __shared__ float ss[128], qq[128];
    int f = blockIdx.x;
    int t = threadIdx.x;
    if (t < 128) {
        float v = 0.f;
#pragma unroll
        for (int k = 0; k < GPART / 128; k++) v += d_part[(t + 128 * k) * 256 + f];
        ss[t] = v;
    } else {
        int tt = t - 128;
        float v = 0.f;
#pragma unroll
        for (int k = 0; k < GPART / 128; k++) v += d_part[(tt + 128 * k) * 256 + 128 + f];
        qq[tt] = v;
    }
    __syncthreads();
#pragma unroll
    for (int off = 64; off > 0; off >>= 1) {
        if (t < off) ss[t] += ss[t + off];
        else if (t >= 128 && t < 128 + off) qq[t - 128] += qq[t - 128 + off];
        __syncthreads();
    }
    if (t == 0) {
        float inv_n = 1.0f / (float)NN;
        float mu = ss[0] * inv_n;
        float ms = qq[0] * inv_n;
        float var = ms - mu * mu;
        float sc = g[f] * rsqrtf(var + 1e-5f);
        d_bnscale[layer * FD + f] = sc;
        d_bnshift[layer * FD + f] = be[f] - mu * sc;
    }
}

__global__ __launch_bounds__(256) void pool_kernel(const void* batch) {
    long long gt = (long long)blockIdx.x * blockDim.x + threadIdx.x;
    long long n = gt >> 5;
    int lane = threadIdx.x & 31;
    if (n >= NN) return;
    int g = load_idx(batch, n);
    int f = lane * 4;
    float4 v = *(const float4*)(d_z + n * FD + f);
    float4 sc = *(const float4*)&d_bnscale[FD + f];
    float4 sh = *(const float4*)&d_bnshift[FD + f];
    v.x = fmaxf(fmaf(v.x, sc.x, sh.x), 0.f);
    v.y = fmaxf(fmaf(v.y, sc.y, sh.y), 0.f);
    v.z = fmaxf(fmaf(v.z, sc.z, sh.z), 0.f);
    v.w = fmaxf(fmaf(v.w, sc.w, sh.w), 0.f);
    red_add_v4(d_pooled + (long long)g * FD + f, v);
}

__global__ void out_kernel(const float* __restrict__ Wout, const float* __restrict__ bout,
                           float* __restrict__ out) {
    int g = blockIdx.x;
    int o = threadIdx.x;
    float inv = 1.0f / fmaxf((float)d_gcnt[g], 1.0f);
    float acc = 0.f;
#pragma unroll 8
    for (int h = 0; h < FD; h++) acc += d_pooled[g * FD + h] * Wout[h * FO + o];
    out[g * FO + o] = acc * inv + bout[o];
}

// ---------------- launch ----------------
extern "C" void kernel_launch(void* const* d_in, const int* in_sizes, int n_in,
                              void* d_out, int out_size) {
    int ii = 0;
    auto nxt = [&]() -> const void* {
        while (ii < n_in && in_sizes[ii] == 1) ii++;
        return d_in[ii++];
    };
    const float* x   = (const float*)nxt();
    const void*  ei  = nxt();
    const void*  bat = nxt();
    const float* W0  = (const float*)nxt();
    const float* b0  = (const float*)nxt();
    const float* g0  = (const float*)nxt();
    const float* be0 = (const float*)nxt();
    const float* W1  = (const float*)nxt();
    const float* b1  = (const float*)nxt();
    const float* g1  = (const float*)nxt();
    const float* be1 = (const float*)nxt();
    const float* Wo  = (const float*)nxt();
    const float* bo  = (const float*)nxt();
    float* out = (float*)d_out;

    static int inited = 0;
    if (!inited) {
        cudaFuncSetAttribute(gemm_mma_kernel, cudaFuncAttributeMaxDynamicSharedMemorySize, GEMM_SMEM);
        inited = 1;
    }

    init_kernel<<<(NN + 255) / 256, 256>>>((const unsigned int*)ei);
    wsplit_kernel<<<64, 256>>>(W0, 0);
    wsplit_kernel<<<64, 256>>>(W1, 1);
    deg_kernel<<<(NE + 255) / 256, 256>>>(ei);
    gemm_mma_kernel<<<GEMM_GRID, 256, GEMM_SMEM>>>(x, 0);
    gcount_kernel<<<(NN + 255) / 256, 256>>>(bat);
    scanA_kernel<<<NBLK, 1024>>>();
    scanB_kernel<<<1, 128>>>();
    scanC_kernel<<<NBLK, 1024>>>();
    csr_fill_kernel<<<(NE + 255) / 256, 256>>>(ei);

    gather_kernel<<<GPART, 256>>>(b0);
    bnstats_kernel<<<FD, 256>>>(g0, be0, 0);

    gemm_mma_kernel<<<GEMM_GRID, 256, GEMM_SMEM>>>(nullptr, 1);
    gather_kernel<<<GPART, 256>>>(b1);
    bnstats_kernel<<<FD, 256>>>(g1, be1, 1);

    pool_kernel<<<(int)(((long long)NN * 32 + 255) / 256), 256>>>(bat);
    out_kernel<<<NG, FO>>>(Wo, bo, out);
}

// round 13
// speedup vs baseline: 1.5385x; 1.1439x over previous
#include <cuda_runtime.h>
#include <cuda_bf16.h>
#include <cstdint>

#define NN 100000
#define NE 1600000
#define FD 128
#define NG 128
#define FO 64
#define NBLK 98            // ceil(NN/1024)
#define GPART 1024         // gather grid / #stat partials
#define GEMM_GRID 782      // ceil(NN/128)
#define LDK 72             // bf16 elements per smem row (144B, ldmatrix conflict-free)
#define GEMM_SMEM (2 * 128 * LDK * 2)   // 36864 B -> 6 CTAs/SM

// ---------------- device scratch ----------------
__device__ __align__(16) unsigned int d_hsb[NN * FD / 2];  // h as bf16 pairs (per layer)
__device__ __align__(16) float d_z[NN * FD];               // pre-BN layer output
__device__ float d_dinv[NN];
__device__ int   d_degcnt[NN];
__device__ int   d_rowtmp[NN];
__device__ int   d_rs[NN + 1];
__device__ int   d_cur[NN];
__device__ int   d_csr[NE];
__device__ int   d_bsum[NBLK];
__device__ int   d_boff[128];
__device__ float d_part[GPART * 256];
__device__ float d_bnscale[2 * FD];
__device__ float d_bnshift[2 * FD];
__device__ __align__(16) float d_pooled[NG * FD];
__device__ int   d_gcnt[NG];
__device__ int   d_is64;
__device__ __align__(16) unsigned short d_whi[2][FD * FD];  // W^T bf16, [n][k]

// ---------------- helpers ----------------
__device__ __forceinline__ uint32_t smem_to_u32(const void* p) {
    uint32_t a;
    asm("{ .reg .u64 t; cvta.to.shared.u64 t, %1; cvt.u32.u64 %0, t; }" : "=r"(a) : "l"(p));
    return a;
}
__device__ __forceinline__ void ldsm_x4(uint32_t addr, uint32_t* r) {
    asm volatile("ldmatrix.sync.aligned.m8n8.x4.shared.b16 {%0,%1,%2,%3}, [%4];"
                 : "=r"(r[0]), "=r"(r[1]), "=r"(r[2]), "=r"(r[3]) : "r"(addr));
}
__device__ __forceinline__ void ldsm_x2(uint32_t addr, uint32_t* r) {
    asm volatile("ldmatrix.sync.aligned.m8n8.x2.shared.b16 {%0,%1}, [%2];"
                 : "=r"(r[0]), "=r"(r[1]) : "r"(addr));
}
__device__ __forceinline__ void mma_bf16(float* c, const uint32_t* a, const uint32_t* b) {
    asm volatile("mma.sync.aligned.m16n8k16.row.col.f32.bf16.bf16.f32 "
                 "{%0,%1,%2,%3}, {%4,%5,%6,%7}, {%8,%9}, {%0,%1,%2,%3};"
                 : "+f"(c[0]), "+f"(c[1]), "+f"(c[2]), "+f"(c[3])
                 : "r"(a[0]), "r"(a[1]), "r"(a[2]), "r"(a[3]), "r"(b[0]), "r"(b[1]));
}
__device__ __forceinline__ int load_idx(const void* p, long long i) {
    if (d_is64) return (int)((const long long*)p)[i];
    return ((const int*)p)[i];
}
__device__ __forceinline__ void red_add_v4(float* dst, float4 v) {
    asm volatile("red.global.add.v4.f32 [%0], {%1, %2, %3, %4};"
                 :: "l"(dst), "f"(v.x), "f"(v.y), "f"(v.z), "f"(v.w) : "memory");
}
__device__ __forceinline__ uint32_t pack_bf2(float a, float b) {
    unsigned short la = __bfloat16_as_ushort(__float2bfloat16(a));
    unsigned short lb = __bfloat16_as_ushort(__float2bfloat16(b));
    return ((uint32_t)lb << 16) | la;
}
__device__ __forceinline__ float blo(uint32_t w) { return __uint_as_float(w << 16); }
__device__ __forceinline__ float bhi(uint32_t w) { return __uint_as_float(w & 0xffff0000u); }

// ---------------- kernels ----------------

// zero init + int64 detection fused
__global__ void init_kernel(const unsigned int* ei32) {
    int i = blockIdx.x * blockDim.x + threadIdx.x;
    if (i < NN) d_degcnt[i] = 0;
    if (i < NG * FD) d_pooled[i] = 0.0f;
    if (i < NG) d_gcnt[i] = 0;
    if (i == 0) {
        int is64 = 1;
        for (int k = 0; k < 128; k++)
            if (ei32[2 * k + 1] != 0u) { is64 = 0; break; }
        d_is64 = is64;
    }
}

// W (fp32 [k][n]) -> bf16 transposed [n][k]
__global__ void wsplit_kernel(const float* __restrict__ W, int which) {
    int i = blockIdx.x * 256 + threadIdx.x;
    int k = i >> 7, n = i & 127;
    d_whi[which][n * FD + k] = __bfloat16_as_ushort(__float2bfloat16(W[i]));
}

// degree histogram + graph-id histogram fused
__global__ void deg_kernel(const void* ei, const void* batch) {
    int i = blockIdx.x * blockDim.x + threadIdx.x;
    if (i < NE) atomicAdd(&d_degcnt[load_idx(ei, (long long)NE + i)], 1);
    if (i < NN) atomicAdd(&d_gcnt[load_idx(batch, i)], 1);
}

__global__ void scanA_kernel() {
    __shared__ int sm[1024];
    int i = blockIdx.x * 1024 + threadIdx.x;
    int v = (i < NN) ? d_degcnt[i] : 0;
    sm[threadIdx.x] = v;
    __syncthreads();
#pragma unroll
    for (int off = 1; off < 1024; off <<= 1) {
        int t = (threadIdx.x >= off) ? sm[threadIdx.x - off] : 0;
        __syncthreads();
        sm[threadIdx.x] += t;
        __syncthreads();
    }
    if (i < NN) d_rowtmp[i] = sm[threadIdx.x];
    if (threadIdx.x == 1023) d_bsum[blockIdx.x] = sm[1023];
}

__global__ void scanB_kernel() {
    __shared__ int sm[128];
    int t = threadIdx.x;
    sm[t] = (t < NBLK) ? d_bsum[t] : 0;
    __syncthreads();
#pragma unroll
    for (int off = 1; off < 128; off <<= 1) {
        int v = (t >= off) ? sm[t - off] : 0;
        __syncthreads();
        sm[t] += v;
        __syncthreads();
    }
    d_boff[t] = sm[t];
}

__global__ void scanC_kernel() {
    int i = blockIdx.x * 1024 + threadIdx.x;
    if (i >= NN) return;
    int blk = blockIdx.x;
    int off = (blk == 0) ? 0 : d_boff[blk - 1];
    int deg = d_degcnt[i];
    int incl = d_rowtmp[i] + off;
    d_rs[i + 1] = incl;
    d_cur[i] = incl - deg;
    d_dinv[i] = rsqrtf((float)(deg + 1));
    if (i == 0) d_rs[0] = 0;
}

__global__ void csr_fill_kernel(const void* ei) {
    int i = blockIdx.x * blockDim.x + threadIdx.x;
    if (i >= NE) return;
    int s = load_idx(ei, i);
    int d = load_idx(ei, (long long)NE + i);
    int pos = atomicAdd(&d_cur[d], 1);
    d_csr[pos] = s;
}

// bf16 tensor-core GEMM via mma.sync, K split in 2 halves (smem reuse -> 6 CTAs/SM).
// d_hsb[tile] = bf16( bnrelu?(A) @ W );  M=128, N=128, K=128, single-term bf16.
__global__ __launch_bounds__(256) void gemm_mma_kernel(const float* __restrict__ Aext, int layer) {
    extern __shared__ __align__(16) char sm_raw[];
    unsigned short* sA = (unsigned short*)sm_raw;            // [128][LDK]
    unsigned short* sB = sA + 128 * LDK;                     // W^T [n][k-half]

    const float* A = (layer == 0) ? Aext : d_z;
    int tid = threadIdx.x;
    int lane = tid & 31, wid = tid >> 5;
    int bm = blockIdx.x * 128;

    int wm = wid & 3, wn = wid >> 2;
    int m0 = wm * 32, n0 = wn * 64;

    float acc[2][8][4];
#pragma unroll
    for (int im = 0; im < 2; im++)
#pragma unroll
        for (int in = 0; in < 8; in++)
#pragma unroll
            for (int c = 0; c < 4; c++) acc[im][in][c] = 0.f;

    int r8 = lane & 7;
    int g1 = (lane >> 3) & 1;
    int g2 = lane >> 4;
    uint32_t aAd = smem_to_u32(sA) + (uint32_t)(((m0 + g1 * 8 + r8) * LDK + g2 * 8) * 2);
    uint32_t bAd = smem_to_u32(sB) + (uint32_t)(((n0 + r8) * LDK + g1 * 8) * 2);

    int srow = tid & 127;               // staging row
    int shalf = tid >> 7;               // 0: cols 0-31, 1: cols 32-63 of the half
    int grow = bm + srow;
    const float* aprow = A + (long long)grow * FD;

#pragma unroll
    for (int kh = 0; kh < 2; kh++) {
        int k0 = kh * 64;
        // ---- stage A (fp32 load, optional BN+ReLU, bf16 convert) ----
#pragma unroll
        for (int g = 0; g < 4; g++) {
            int c = shalf * 32 + g * 8;          // col within half
            int f = k0 + c;                      // global feature col
            float4 v0 = make_float4(0.f, 0.f, 0.f, 0.f);
            float4 v1 = v0;
            if (grow < NN) {
                v0 = *(const float4*)(aprow + f);
                v1 = *(const float4*)(aprow + f + 4);
            }
            if (layer == 1) {
                float4 sc0 = *(const float4*)&d_bnscale[f];
                float4 sh0 = *(const float4*)&d_bnshift[f];
                float4 sc1 = *(const float4*)&d_bnscale[f + 4];
                float4 sh1 = *(const float4*)&d_bnshift[f + 4];
                v0.x = fmaxf(fmaf(v0.x, sc0.x, sh0.x), 0.f);
                v0.y = fmaxf(fmaf(v0.y, sc0.y, sh0.y), 0.f);
                v0.z = fmaxf(fmaf(v0.z, sc0.z, sh0.z), 0.f);
                v0.w = fmaxf(fmaf(v0.w, sc0.w, sh0.w), 0.f);
                v1.x = fmaxf(fmaf(v1.x, sc1.x, sh1.x), 0.f);
                v1.y = fmaxf(fmaf(v1.y, sc1.y, sh1.y), 0.f);
                v1.z = fmaxf(fmaf(v1.z, sc1.z, sh1.z), 0.f);
                v1.w = fmaxf(fmaf(v1.w, sc1.w, sh1.w), 0.f);
            }
            uint4 hi;
            hi.x = pack_bf2(v0.x, v0.y); hi.y = pack_bf2(v0.z, v0.w);
            hi.z = pack_bf2(v1.x, v1.y); hi.w = pack_bf2(v1.z, v1.w);
            *(uint4*)(sA + srow * LDK + c) = hi;
        }
        // ---- stage B (copy pre-converted W^T) ----
        {
            const unsigned short* wh = &d_whi[layer][srow * FD + k0 + shalf * 32];
#pragma unroll
            for (int g = 0; g < 4; g++)
                *(uint4*)(sB + srow * LDK + shalf * 32 + g * 8) = *(const uint4*)(wh + g * 8);
        }
        __syncthreads();

        // ---- compute 4 k-steps of this half ----
#pragma unroll
        for (int ks = 0; ks < 4; ks++) {
            uint32_t ko = ks * 32;
            uint32_t av[2][4];
            ldsm_x4(aAd + ko, av[0]);
            ldsm_x4(aAd + 16 * LDK * 2 + ko, av[1]);
            uint32_t bv[8][2];
#pragma unroll
            for (int in = 0; in < 8; in++)
                ldsm_x2(bAd + in * (8 * LDK * 2) + ko, bv[in]);
#pragma unroll
            for (int im = 0; im < 2; im++)
#pragma unroll
                for (int in = 0; in < 8; in++)
                    mma_bf16(acc[im][in], av[im], bv[in]);
        }
        __syncthreads();
    }

    // ---- epilogue: acc -> d_hsb (bf16 pairs) ----
    int rlo = lane >> 2;
    int cbase = (lane & 3) * 2;
#pragma unroll
    for (int im = 0; im < 2; im++) {
        int row0 = bm + m0 + im * 16 + rlo;
        int row1 = row0 + 8;
#pragma unroll
        for (int in = 0; in < 8; in++) {
            int col = n0 + in * 8 + cbase;
            if (row0 < NN)
                d_hsb[(long long)row0 * 64 + (col >> 1)] = pack_bf2(acc[im][in][0], acc[im][in][1]);
            if (row1 < NN)
                d_hsb[(long long)row1 * 64 + (col >> 1)] = pack_bf2(acc[im][in][2], acc[im][in][3]);
        }
    }
}

// warp per node (strided): z[n] = dinv[n]*( sum_nbr dinv[s]*h[s] + dinv[n]*h[n] ) + bias
__global__ __launch_bounds__(256) void gather_kernel(const float* __restrict__ bias) {
    __shared__ float red[8][256];
    int lane = threadIdx.x & 31;
    int warp = threadIdx.x >> 5;
    int gw = blockIdx.x * 8 + warp;
    float b0 = bias[lane * 4 + 0];
    float b1 = bias[lane * 4 + 1];
    float b2 = bias[lane * 4 + 2];
    float b3 = bias[lane * 4 + 3];

    float4 s = make_float4(0.f, 0.f, 0.f, 0.f);
    float4 q = make_float4(0.f, 0.f, 0.f, 0.f);

    for (int n = gw; n < NN; n += GPART * 8) {
        int rs = d_rs[n];
        int re = d_rs[n + 1];
        float dv = d_dinv[n];
        uint2 sv = __ldg((const uint2*)(d_hsb + (long long)n * 64) + lane);
        float4 acc = make_float4(blo(sv.x) * dv, bhi(sv.x) * dv, blo(sv.y) * dv, bhi(sv.y) * dv);

        int j = rs;
        for (; j + 4 <= re; j += 4) {
            int i0 = d_csr[j], i1 = d_csr[j + 1], i2 = d_csr[j + 2], i3 = d_csr[j + 3];
            float e0 = d_dinv[i0], e1 = d_dinv[i1], e2 = d_dinv[i2], e3 = d_dinv[i3];
            uint2 v0 = __ldg((const uint2*)(d_hsb + (long long)i0 * 64) + lane);
            uint2 v1 = __ldg((const uint2*)(d_hsb + (long long)i1 * 64) + lane);
            uint2 v2 = __ldg((const uint2*)(d_hsb + (long long)i2 * 64) + lane);
            uint2 v3 = __ldg((const uint2*)(d_hsb + (long long)i3 * 64) + lane);
            acc.x = fmaf(blo(v0.x), e0, acc.x); acc.y = fmaf(bhi(v0.x), e0, acc.y);
            acc.z = fmaf(blo(v0.y), e0, acc.z); acc.w = fmaf(bhi(v0.y), e0, acc.w);
            acc.x = fmaf(blo(v1.x), e1, acc.x); acc.y = fmaf(bhi(v1.x), e1, acc.y);
            acc.z = fmaf(blo(v1.y), e1, acc.z); acc.w = fmaf(bhi(v1.y), e1, acc.w);
            acc.x = fmaf(blo(v2.x), e2, acc.x); acc.y = fmaf(bhi(v2.x), e2, acc.y);
            acc.z = fmaf(blo(v2.y), e2, acc.z); acc.w = fmaf(bhi(v2.y), e2, acc.w);
            acc.x = fmaf(blo(v3.x), e3, acc.x); acc.y = fmaf(bhi(v3.x), e3, acc.y);
            acc.z = fmaf(blo(v3.y), e3, acc.z); acc.w = fmaf(bhi(v3.y), e3, acc.w);
        }
        for (; j < re; j++) {
            int i0 = d_csr[j];
            float e0 = d_dinv[i0];
            uint2 v0 = __ldg((const uint2*)(d_hsb + (long long)i0 * 64) + lane);
            acc.x = fmaf(blo(v0.x), e0, acc.x); acc.y = fmaf(bhi(v0.x), e0, acc.y);
            acc.z = fmaf(blo(v0.y), e0, acc.z); acc.w = fmaf(bhi(v0.y), e0, acc.w);
        }

        float4 z;
        z.x = fmaf(acc.x, dv, b0);
        z.y = fmaf(acc.y, dv, b1);
        z.z = fmaf(acc.z, dv, b2);
        z.w = fmaf(acc.w, dv, b3);
        *((float4*)(d_z + (long long)n * FD) + lane) = z;

        s.x += z.x; s.y += z.y; s.z += z.z; s.w += z.w;
        q.x = fmaf(z.x, z.x, q.x); q.y = fmaf(z.y, z.y, q.y);
        q.z = fmaf(z.z, z.z, q.z); q.w = fmaf(z.w, z.w, q.w);
    }

    red[warp][lane * 4 + 0] = s.x; red[warp][lane * 4 + 1] = s.y;
    red[warp][lane * 4 + 2] = s.z; red[warp][lane * 4 + 3] = s.w;
    red[warp][128 + lane * 4 + 0] = q.x; red[warp][128 + lane * 4 + 1] = q.y;
    red[warp][128 + lane * 4 + 2] = q.z; red[warp][128 + lane * 4 + 3] = q.w;
    __syncthreads();
    int c = threadIdx.x;
    float t = 0.f;
#pragma unroll
    for (int w = 0; w < 8; w++) t += red[w][c];
    d_part[blockIdx.x * 256 + c] = t;
}

__global__ void bnstats_kernel(const float* __restrict__ g, const float* __restrict__ be, int layer) {
    __shared__ float ss[128], qq[128];
    int f = blockIdx.x;
    int t = threadIdx.x;
    if (t < 128) {
        float v = 0.f;
#pragma unroll
        for (int k = 0; k < GPART / 128; k++) v += d_part[(t + 128 * k) * 256 + f];
        ss[t] = v;
    } else {
        int tt = t - 128;
        float v = 0.f;
#pragma unroll
        for (int k = 0; k < GPART / 128; k++) v += d_part[(tt + 128 * k) * 256 + 128 + f];
        qq[tt] = v;
    }
    __syncthreads();
#pragma unroll
    for (int off = 64; off > 0; off >>= 1) {
        if (t < off) ss[t] += ss[t + off];
        else if (t >= 128 && t < 128 + off) qq[t - 128] += qq[t - 128 + off];
        __syncthreads();
    }
    if (t == 0) {
        float inv_n = 1.0f / (float)NN;
        float mu = ss[0] * inv_n;
        float ms = qq[0] * inv_n;
        float var = ms - mu * mu;
        float sc = g[f] * rsqrtf(var + 1e-5f);
        d_bnscale[layer * FD + f] = sc;
        d_bnshift[layer * FD + f] = be[f] - mu * sc;
    }
}

__global__ __launch_bounds__(256) void pool_kernel(const void* batch) {
    long long gt = (long long)blockIdx.x * blockDim.x + threadIdx.x;
    long long n = gt >> 5;
    int lane = threadIdx.x & 31;
    if (n >= NN) return;
    int g = load_idx(batch, n);
    int f = lane * 4;
    float4 v = *(const float4*)(d_z + n * FD + f);
    float4 sc = *(const float4*)&d_bnscale[FD + f];
    float4 sh = *(const float4*)&d_bnshift[FD + f];
    v.x = fmaxf(fmaf(v.x, sc.x, sh.x), 0.f);
    v.y = fmaxf(fmaf(v.y, sc.y, sh.y), 0.f);
    v.z = fmaxf(fmaf(v.z, sc.z, sh.z), 0.f);
    v.w = fmaxf(fmaf(v.w, sc.w, sh.w), 0.f);
    red_add_v4(d_pooled + (long long)g * FD + f, v);
}

__global__ void out_kernel(const float* __restrict__ Wout, const float* __restrict__ bout,
                           float* __restrict__ out) {
    int g = blockIdx.x;
    int o = threadIdx.x;
    float inv = 1.0f / fmaxf((float)d_gcnt[g], 1.0f);
    float acc = 0.f;
#pragma unroll 8
    for (int h = 0; h < FD; h++) acc += d_pooled[g * FD + h] * Wout[h * FO + o];
    out[g * FO + o] = acc * inv + bout[o];
}

// ---------------- launch ----------------
extern "C" void kernel_launch(void* const* d_in, const int* in_sizes, int n_in,
                              void* d_out, int out_size) {
    int ii = 0;
    auto nxt = [&]() -> const void* {
        while (ii < n_in && in_sizes[ii] == 1) ii++;
        return d_in[ii++];
    };
    const float* x   = (const float*)nxt();
    const void*  ei  = nxt();
    const void*  bat = nxt();
    const float* W0  = (const float*)nxt();
    const float* b0  = (const float*)nxt();
    const float* g0  = (const float*)nxt();
    const float* be0 = (const float*)nxt();
    const float* W1  = (const float*)nxt();
    const float* b1  = (const float*)nxt();
    const float* g1  = (const float*)nxt();
    const float* be1 = (const float*)nxt();
    const float* Wo  = (const float*)nxt();
    const float* bo  = (const float*)nxt();
    float* out = (float*)d_out;

    static int inited = 0;
    if (!inited) {
        cudaFuncSetAttribute(gemm_mma_kernel, cudaFuncAttributeMaxDynamicSharedMemorySize, GEMM_SMEM);
        inited = 1;
    }

    init_kernel<<<(NN + 255) / 256, 256>>>((const unsigned int*)ei);
    wsplit_kernel<<<64, 256>>>(W0, 0);
    wsplit_kernel<<<64, 256>>>(W1, 1);
    deg_kernel<<<(NE + 255) / 256, 256>>>(ei, bat);
    gemm_mma_kernel<<<GEMM_GRID, 256, GEMM_SMEM>>>(x, 0);
    scanA_kernel<<<NBLK, 1024>>>();
    scanB_kernel<<<1, 128>>>();
    scanC_kernel<<<NBLK, 1024>>>();
    csr_fill_kernel<<<(NE + 255) / 256, 256>>>(ei);

    gather_kernel<<<GPART, 256>>>(b0);
    bnstats_kernel<<<FD, 256>>>(g0, be0, 0);

    gemm_mma_kernel<<<GEMM_GRID, 256, GEMM_SMEM>>>(nullptr, 1);
    gather_kernel<<<GPART, 256>>>(b1);
    bnstats_kernel<<<FD, 256>>>(g1, be1, 1);

    pool_kernel<<<(int)(((long long)NN * 32 + 255) / 256), 256>>>(bat);
    out_kernel<<<NG, FO>>>(Wo, bo, out);
}

// round 14
// speedup vs baseline: 1.6728x; 1.0873x over previous
#include <cuda_runtime.h>
#include <cuda_bf16.h>
#include <cstdint>

#define NN 100000
#define NE 1600000
#define FD 128
#define NG 128
#define FO 64
#define NBLK 98            // ceil(NN/1024)
#define GPART 1024         // gather grid / #stat partials
#define GEMM_GRID 782      // ceil(NN/128)
#define LDK 72             // bf16 elements per smem row (144B, ldmatrix conflict-free)
#define GEMM_SMEM (2 * 128 * LDK * 2)   // 36864 B -> 6 CTAs/SM

// ---------------- device scratch ----------------
__device__ __align__(16) unsigned int d_hsb[NN * FD / 2];  // h as bf16 pairs (per layer)
__device__ __align__(16) unsigned int d_zb[NN * FD / 2];   // z (pre-BN) as bf16 pairs
__device__ float d_dinv[NN];
__device__ int   d_degcnt[NN];
__device__ int   d_rowtmp[NN];
__device__ int   d_rs[NN + 1];
__device__ int   d_cur[NN];
__device__ int   d_csr[NE];
__device__ int   d_bsum[NBLK];
__device__ float d_part[GPART * 256];
__device__ float d_bnscale[2 * FD];
__device__ float d_bnshift[2 * FD];
__device__ __align__(16) float d_pooled[NG * FD];
__device__ int   d_gstart[NG];
__device__ int   d_gend[NG];
__device__ int   d_is64;
__device__ __align__(16) unsigned short d_whi[2][FD * FD];  // W^T bf16, [n][k]

// ---------------- helpers ----------------
__device__ __forceinline__ uint32_t smem_to_u32(const void* p) {
    uint32_t a;
    asm("{ .reg .u64 t; cvta.to.shared.u64 t, %1; cvt.u32.u64 %0, t; }" : "=r"(a) : "l"(p));
    return a;
}
__device__ __forceinline__ void ldsm_x4(uint32_t addr, uint32_t* r) {
    asm volatile("ldmatrix.sync.aligned.m8n8.x4.shared.b16 {%0,%1,%2,%3}, [%4];"
                 : "=r"(r[0]), "=r"(r[1]), "=r"(r[2]), "=r"(r[3]) : "r"(addr));
}
__device__ __forceinline__ void ldsm_x2(uint32_t addr, uint32_t* r) {
    asm volatile("ldmatrix.sync.aligned.m8n8.x2.shared.b16 {%0,%1}, [%2];"
                 : "=r"(r[0]), "=r"(r[1]) : "r"(addr));
}
__device__ __forceinline__ void mma_bf16(float* c, const uint32_t* a, const uint32_t* b) {
    asm volatile("mma.sync.aligned.m16n8k16.row.col.f32.bf16.bf16.f32 "
                 "{%0,%1,%2,%3}, {%4,%5,%6,%7}, {%8,%9}, {%0,%1,%2,%3};"
                 : "+f"(c[0]), "+f"(c[1]), "+f"(c[2]), "+f"(c[3])
                 : "r"(a[0]), "r"(a[1]), "r"(a[2]), "r"(a[3]), "r"(b[0]), "r"(b[1]));
}
__device__ __forceinline__ int load_idx(const void* p, long long i) {
    if (d_is64) return (int)((const long long*)p)[i];
    return ((const int*)p)[i];
}
__device__ __forceinline__ void red_add_v4(float* dst, float4 v) {
    asm volatile("red.global.add.v4.f32 [%0], {%1, %2, %3, %4};"
                 :: "l"(dst), "f"(v.x), "f"(v.y), "f"(v.z), "f"(v.w) : "memory");
}
__device__ __forceinline__ uint32_t pack_bf2(float a, float b) {
    unsigned short la = __bfloat16_as_ushort(__float2bfloat16(a));
    unsigned short lb = __bfloat16_as_ushort(__float2bfloat16(b));
    return ((uint32_t)lb << 16) | la;
}
__device__ __forceinline__ float blo(uint32_t w) { return __uint_as_float(w << 16); }
__device__ __forceinline__ float bhi(uint32_t w) { return __uint_as_float(w & 0xffff0000u); }

// ---------------- kernels ----------------

// zero init + int64 detection fused
__global__ void init_kernel(const unsigned int* ei32) {
    int i = blockIdx.x * blockDim.x + threadIdx.x;
    if (i < NN) d_degcnt[i] = 0;
    if (i < NG * FD) d_pooled[i] = 0.0f;
    if (i < NG) { d_gstart[i] = 0; d_gend[i] = 0; }
    if (i == 0) {
        int is64 = 1;
        for (int k = 0; k < 128; k++)
            if (ei32[2 * k + 1] != 0u) { is64 = 0; break; }
        d_is64 = is64;
    }
}

// both W matrices (fp32 [k][n]) -> bf16 transposed [n][k]
__global__ void wsplit_kernel(const float* __restrict__ W0, const float* __restrict__ W1) {
    int b = blockIdx.x;
    int which = b >> 6;
    int i = (b & 63) * 256 + threadIdx.x;
    const float* W = which ? W1 : W0;
    int k = i >> 7, n = i & 127;
    d_whi[which][n * FD + k] = __bfloat16_as_ushort(__float2bfloat16(W[i]));
}

__global__ void deg_kernel(const void* ei) {
    int i = blockIdx.x * blockDim.x + threadIdx.x;
    if (i < NE) atomicAdd(&d_degcnt[load_idx(ei, (long long)NE + i)], 1);
}

__global__ void scanA_kernel() {
    __shared__ int sm[1024];
    int i = blockIdx.x * 1024 + threadIdx.x;
    int v = (i < NN) ? d_degcnt[i] : 0;
    sm[threadIdx.x] = v;
    __syncthreads();
#pragma unroll
    for (int off = 1; off < 1024; off <<= 1) {
        int t = (threadIdx.x >= off) ? sm[threadIdx.x - off] : 0;
        __syncthreads();
        sm[threadIdx.x] += t;
        __syncthreads();
    }
    if (i < NN) d_rowtmp[i] = sm[threadIdx.x];
    if (threadIdx.x == 1023) d_bsum[blockIdx.x] = sm[1023];
}

// finalize row pointers/cursors/dinv (block prefix computed locally) + batch segment bounds
__global__ void scanC_kernel(const void* batch) {
    __shared__ int red[128];
    int t = threadIdx.x;
    int blk = blockIdx.x;
    if (t < 128) red[t] = (t < blk && t < NBLK) ? d_bsum[t] : 0;
    __syncthreads();
#pragma unroll
    for (int off = 64; off > 0; off >>= 1) {
        if (t < off) red[t] += red[t + off];
        __syncthreads();
    }
    int off0 = red[0];
    int i = blk * 1024 + t;
    if (i >= NN) return;
    int deg = d_degcnt[i];
    int incl = d_rowtmp[i] + off0;
    d_rs[i + 1] = incl;
    d_cur[i] = incl - deg;
    d_dinv[i] = rsqrtf((float)(deg + 1));
    if (i == 0) d_rs[0] = 0;
    // sorted-batch segment boundaries -> per-graph [start,end)
    int b = load_idx(batch, i);
    if (i == 0 || load_idx(batch, i - 1) != b) d_gstart[b] = i;
    if (i == NN - 1 || load_idx(batch, i + 1) != b) d_gend[b] = i + 1;
}

__global__ void csr_fill_kernel(const void* ei) {
    int i = blockIdx.x * blockDim.x + threadIdx.x;
    if (i >= NE) return;
    int s = load_idx(ei, i);
    int d = load_idx(ei, (long long)NE + i);
    int pos = atomicAdd(&d_cur[d], 1);
    d_csr[pos] = s;
}

// bf16 tensor-core GEMM via mma.sync, K split in 2 halves (smem reuse -> 6 CTAs/SM).
// d_hsb[tile] = bf16( bnrelu?(A) @ W );  layer0: A = x (fp32); layer1: A = d_zb (bf16) + BN/ReLU.
__global__ __launch_bounds__(256) void gemm_mma_kernel(const float* __restrict__ Aext, int layer) {
    extern __shared__ __align__(16) char sm_raw[];
    unsigned short* sA = (unsigned short*)sm_raw;            // [128][LDK]
    unsigned short* sB = sA + 128 * LDK;                     // W^T [n][k-half]

    int tid = threadIdx.x;
    int lane = tid & 31, wid = tid >> 5;
    int bm = blockIdx.x * 128;

    int wm = wid & 3, wn = wid >> 2;
    int m0 = wm * 32, n0 = wn * 64;

    float acc[2][8][4];
#pragma unroll
    for (int im = 0; im < 2; im++)
#pragma unroll
        for (int in = 0; in < 8; in++)
#pragma unroll
            for (int c = 0; c < 4; c++) acc[im][in][c] = 0.f;

    int r8 = lane & 7;
    int g1 = (lane >> 3) & 1;
    int g2 = lane >> 4;
    uint32_t aAd = smem_to_u32(sA) + (uint32_t)(((m0 + g1 * 8 + r8) * LDK + g2 * 8) * 2);
    uint32_t bAd = smem_to_u32(sB) + (uint32_t)(((n0 + r8) * LDK + g1 * 8) * 2);

    int srow = tid & 127;               // staging row
    int shalf = tid >> 7;               // 0: cols 0-31, 1: cols 32-63 of the half
    int grow = bm + srow;
    const float* aprow = Aext + (long long)grow * FD;
    const uint4* zprow = (const uint4*)(d_zb + (long long)grow * 64);

#pragma unroll
    for (int kh = 0; kh < 2; kh++) {
        int k0 = kh * 64;
        // ---- stage A ----
#pragma unroll
        for (int g = 0; g < 4; g++) {
            int c = shalf * 32 + g * 8;          // col within half
            int f = k0 + c;                      // global feature col
            float v[8];
            if (layer == 0) {
                float4 v0 = make_float4(0.f, 0.f, 0.f, 0.f), v1 = v0;
                if (grow < NN) {
                    v0 = *(const float4*)(aprow + f);
                    v1 = *(const float4*)(aprow + f + 4);
                }
                v[0] = v0.x; v[1] = v0.y; v[2] = v0.z; v[3] = v0.w;
                v[4] = v1.x; v[5] = v1.y; v[6] = v1.z; v[7] = v1.w;
            } else {
                uint4 zv = make_uint4(0u, 0u, 0u, 0u);
                if (grow < NN) zv = zprow[f >> 3];
                v[0] = blo(zv.x); v[1] = bhi(zv.x); v[2] = blo(zv.y); v[3] = bhi(zv.y);
                v[4] = blo(zv.z); v[5] = bhi(zv.z); v[6] = blo(zv.w); v[7] = bhi(zv.w);
#pragma unroll
                for (int e = 0; e < 8; e++)
                    v[e] = fmaxf(fmaf(v[e], d_bnscale[f + e], d_bnshift[f + e]), 0.f);
            }
            uint4 hi;
            hi.x = pack_bf2(v[0], v[1]); hi.y = pack_bf2(v[2], v[3]);
            hi.z = pack_bf2(v[4], v[5]); hi.w = pack_bf2(v[6], v[7]);
            *(uint4*)(sA + srow * LDK + c) = hi;
        }
        // ---- stage B (copy pre-converted W^T) ----
        {
            const unsigned short* wh = &d_whi[layer][srow * FD + k0 + shalf * 32];
#pragma unroll
            for (int g = 0; g < 4; g++)
                *(uint4*)(sB + srow * LDK + shalf * 32 + g * 8) = *(const uint4*)(wh + g * 8);
        }
        __syncthreads();

        // ---- compute 4 k-steps of this half ----
#pragma unroll
        for (int ks = 0; ks < 4; ks++) {
            uint32_t ko = ks * 32;
            uint32_t av[2][4];
            ldsm_x4(aAd + ko, av[0]);
            ldsm_x4(aAd + 16 * LDK * 2 + ko, av[1]);
            uint32_t bv[8][2];
#pragma unroll
            for (int in = 0; in < 8; in++)
                ldsm_x2(bAd + in * (8 * LDK * 2) + ko, bv[in]);
#pragma unroll
            for (int im = 0; im < 2; im++)
#pragma unroll
                for (int in = 0; in < 8; in++)
                    mma_bf16(acc[im][in], av[im], bv[in]);
        }
        __syncthreads();
    }

    // ---- epilogue: acc -> d_hsb (bf16 pairs) ----
    int rlo = lane >> 2;
    int cbase = (lane & 3) * 2;
#pragma unroll
    for (int im = 0; im < 2; im++) {
        int row0 = bm + m0 + im * 16 + rlo;
        int row1 = row0 + 8;
#pragma unroll
        for (int in = 0; in < 8; in++) {
            int col = n0 + in * 8 + cbase;
            if (row0 < NN)
                d_hsb[(long long)row0 * 64 + (col >> 1)] = pack_bf2(acc[im][in][0], acc[im][in][1]);
            if (row1 < NN)
                d_hsb[(long long)row1 * 64 + (col >> 1)] = pack_bf2(acc[im][in][2], acc[im][in][3]);
        }
    }
}

// warp per node (strided): z[n] = dinv[n]*( sum_nbr dinv[s]*h[s] + dinv[n]*h[n] ) + bias
// h read as bf16 pairs; z written as bf16 pairs; BN stats accumulated in fp32.
__global__ __launch_bounds__(256) void gather_kernel(const float* __restrict__ bias) {
    __shared__ float red[8][256];
    int lane = threadIdx.x & 31;
    int warp = threadIdx.x >> 5;
    int gw = blockIdx.x * 8 + warp;
    float b0 = bias[lane * 4 + 0];
    float b1 = bias[lane * 4 + 1];
    float b2 = bias[lane * 4 + 2];
    float b3 = bias[lane * 4 + 3];

    float4 s = make_float4(0.f, 0.f, 0.f, 0.f);
    float4 q = make_float4(0.f, 0.f, 0.f, 0.f);

    for (int n = gw; n < NN; n += GPART * 8) {
        int rs = d_rs[n];
        int re = d_rs[n + 1];
        float dv = d_dinv[n];
        uint2 sv = __ldg((const uint2*)(d_hsb + (long long)n * 64) + lane);
        float4 acc = make_float4(blo(sv.x) * dv, bhi(sv.x) * dv, blo(sv.y) * dv, bhi(sv.y) * dv);

        int j = rs;
        for (; j + 4 <= re; j += 4) {
            int i0 = d_csr[j], i1 = d_csr[j + 1], i2 = d_csr[j + 2], i3 = d_csr[j + 3];
            float e0 = d_dinv[i0], e1 = d_dinv[i1], e2 = d_dinv[i2], e3 = d_dinv[i3];
            uint2 v0 = __ldg((const uint2*)(d_hsb + (long long)i0 * 64) + lane);
            uint2 v1 = __ldg((const uint2*)(d_hsb + (long long)i1 * 64) + lane);
            uint2 v2 = __ldg((const uint2*)(d_hsb + (long long)i2 * 64) + lane);
            uint2 v3 = __ldg((const uint2*)(d_hsb + (long long)i3 * 64) + lane);
            acc.x = fmaf(blo(v0.x), e0, acc.x); acc.y = fmaf(bhi(v0.x), e0, acc.y);
            acc.z = fmaf(blo(v0.y), e0, acc.z); acc.w = fmaf(bhi(v0.y), e0, acc.w);
            acc.x = fmaf(blo(v1.x), e1, acc.x); acc.y = fmaf(bhi(v1.x), e1, acc.y);
            acc.z = fmaf(blo(v1.y), e1, acc.z); acc.w = fmaf(bhi(v1.y), e1, acc.w);
            acc.x = fmaf(blo(v2.x), e2, acc.x); acc.y = fmaf(bhi(v2.x), e2, acc.y);
            acc.z = fmaf(blo(v2.y), e2, acc.z); acc.w = fmaf(bhi(v2.y), e2, acc.w);
            acc.x = fmaf(blo(v3.x), e3, acc.x); acc.y = fmaf(bhi(v3.x), e3, acc.y);
            acc.z = fmaf(blo(v3.y), e3, acc.z); acc.w = fmaf(bhi(v3.y), e3, acc.w);
        }
        for (; j < re; j++) {
            int i0 = d_csr[j];
            float e0 = d_dinv[i0];
            uint2 v0 = __ldg((const uint2*)(d_hsb + (long long)i0 * 64) + lane);
            acc.x = fmaf(blo(v0.x), e0, acc.x); acc.y = fmaf(bhi(v0.x), e0, acc.y);
            acc.z = fmaf(blo(v0.y), e0, acc.z); acc.w = fmaf(bhi(v0.y), e0, acc.w);
        }

        float4 z;
        z.x = fmaf(acc.x, dv, b0);
        z.y = fmaf(acc.y, dv, b1);
        z.z = fmaf(acc.z, dv, b2);
        z.w = fmaf(acc.w, dv, b3);
        uint2 zp;
        zp.x = pack_bf2(z.x, z.y);
        zp.y = pack_bf2(z.z, z.w);
        *((uint2*)(d_zb + (long long)n * 64) + lane) = zp;

        s.x += z.x; s.y += z.y; s.z += z.z; s.w += z.w;
        q.x = fmaf(z.x, z.x, q.x); q.y = fmaf(z.y, z.y, q.y);
        q.z = fmaf(z.z, z.z, q.z); q.w = fmaf(z.w, z.w, q.w);
    }

    red[warp][lane * 4 + 0] = s.x; red[warp][lane * 4 + 1] = s.y;
    red[warp][lane * 4 + 2] = s.z; red[warp][lane * 4 + 3] = s.w;
    red[warp][128 + lane * 4 + 0] = q.x; red[warp][128 + lane * 4 + 1] = q.y;
    red[warp][128 + lane * 4 + 2] = q.z; red[warp][128 + lane * 4 + 3] = q.w;
    __syncthreads();
    int c = threadIdx.x;
    float t = 0.f;
#pragma unroll
    for (int w = 0; w < 8; w++) t += red[w][c];
    d_part[blockIdx.x * 256 + c] = t;
}

__global__ void bnstats_kernel(const float* __restrict__ g, const float* __restrict__ be, int layer) {
    __shared__ float ss[128], qq[128];
    int f = blockIdx.x;
    int t = threadIdx.x;
    if (t < 128) {
        float v = 0.f;
#pragma unroll
        for (int k = 0; k < GPART / 128; k++) v += d_part[(t + 128 * k) * 256 + f];
        ss[t] = v;
    } else {
        int tt = t - 128;
        float v = 0.f;
#pragma unroll
        for (int k = 0; k < GPART / 128; k++) v += d_part[(tt + 128 * k) * 256 + 128 + f];
        qq[tt] = v;
    }
    __syncthreads();
#pragma unroll
    for (int off = 64; off > 0; off >>= 1) {
        if (t < off) ss[t] += ss[t + off];
        else if (t >= 128 && t < 128 + off) qq[t - 128] += qq[t - 128 + off];
        __syncthreads();
    }
    if (t == 0) {
        float inv_n = 1.0f / (float)NN;
        float mu = ss[0] * inv_n;
        float ms = qq[0] * inv_n;
        float var = ms - mu * mu;
        float sc = g[f] * rsqrtf(var + 1e-5f);
        d_bnscale[layer * FD + f] = sc;
        d_bnshift[layer * FD + f] = be[f] - mu * sc;
    }
}

// warp per node: pooled[batch[n]] += relu(bn1(z[n]))  (z read as bf16)
__global__ __launch_bounds__(256) void pool_kernel(const void* batch) {
    long long gt = (long long)blockIdx.x * blockDim.x + threadIdx.x;
    long long n = gt >> 5;
    int lane = threadIdx.x & 31;
    if (n >= NN) return;
    int g = load_idx(batch, n);
    int f = lane * 4;
    uint2 zv = *((const uint2*)(d_zb + n * 64) + lane);
    float4 v = make_float4(blo(zv.x), bhi(zv.x), blo(zv.y), bhi(zv.y));
    float4 sc = *(const float4*)&d_bnscale[FD + f];
    float4 sh = *(const float4*)&d_bnshift[FD + f];
    v.x = fmaxf(fmaf(v.x, sc.x, sh.x), 0.f);
    v.y = fmaxf(fmaf(v.y, sc.y, sh.y), 0.f);
    v.z = fmaxf(fmaf(v.z, sc.z, sh.z), 0.f);
    v.w = fmaxf(fmaf(v.w, sc.w, sh.w), 0.f);
    red_add_v4(d_pooled + (long long)g * FD + f, v);
}

__global__ void out_kernel(const float* __restrict__ Wout, const float* __restrict__ bout,
                           float* __restrict__ out) {
    int g = blockIdx.x;
    int o = threadIdx.x;
    int cnt = d_gend[g] - d_gstart[g];
    float inv = 1.0f / fmaxf((float)cnt, 1.0f);
    float acc = 0.f;
#pragma unroll 8
    for (int h = 0; h < FD; h++) acc += d_pooled[g * FD + h] * Wout[h * FO + o];
    out[g * FO + o] = acc * inv + bout[o];
}

// ---------------- launch ----------------
extern "C" void kernel_launch(void* const* d_in, const int* in_sizes, int n_in,
                              void* d_out, int out_size) {
    int ii = 0;
    auto nxt = [&]() -> const void* {
        while (ii < n_in && in_sizes[ii] == 1) ii++;
        return d_in[ii++];
    };
    const float* x   = (const float*)nxt();
    const void*  ei  = nxt();
    const void*  bat = nxt();
    const float* W0  = (const float*)nxt();
    const float* b0  = (const float*)nxt();
    const float* g0  = (const float*)nxt();
    const float* be0 = (const float*)nxt();
    const float* W1  = (const float*)nxt();
    const float* b1  = (const float*)nxt();
    const float* g1  = (const float*)nxt();
    const float* be1 = (const float*)nxt();
    const float* Wo  = (const float*)nxt();
    const float* bo  = (const float*)nxt();
    float* out = (float*)d_out;

    static int inited = 0;
    if (!inited) {
        cudaFuncSetAttribute(gemm_mma_kernel, cudaFuncAttributeMaxDynamicSharedMemorySize, GEMM_SMEM);
        inited = 1;
    }

    init_kernel<<<(NN + 255) / 256, 256>>>((const unsigned int*)ei);
    wsplit_kernel<<<128, 256>>>(W0, W1);
    deg_kernel<<<(NE + 255) / 256, 256>>>(ei);
    gemm_mma_kernel<<<GEMM_GRID, 256, GEMM_SMEM>>>(x, 0);
    scanA_kernel<<<NBLK, 1024>>>();
    scanC_kernel<<<NBLK, 1024>>>(bat);
    csr_fill_kernel<<<(NE + 255) / 256, 256>>>(ei);

    gather_kernel<<<GPART, 256>>>(b0);
    bnstats_kernel<<<FD, 256>>>(g0, be0, 0);

    gemm_mma_kernel<<<GEMM_GRID, 256, GEMM_SMEM>>>(x, 1);
    gather_kernel<<<GPART, 256>>>(b1);
    bnstats_kernel<<<FD, 256>>>(g1, be1, 1);

    pool_kernel<<<(int)(((long long)NN * 32 + 255) / 256), 256>>>(bat);
    out_kernel<<<NG, FO>>>(Wo, bo, out);
}